// round 1
// baseline (speedup 1.0000x reference)
#include <cuda_runtime.h>
#include <cstdint>
#include <cstddef>

#define NN 512
#define CC 128
#define CP 64   // channel pairs

typedef unsigned long long ull;

// ---------------- f32x2 packed math helpers (Blackwell FFMA2 path) ----------
__device__ __forceinline__ ull ffma2(ull a, ull b, ull c){
    ull d;
    asm("fma.rn.f32x2 %0, %1, %2, %3;" : "=l"(d) : "l"(a), "l"(b), "l"(c));
    return d;
}
__device__ __forceinline__ ull pack2(float x, float y){
    ull r; asm("mov.b64 %0, {%1, %2};" : "=l"(r) : "f"(x), "f"(y)); return r;
}
__device__ __forceinline__ float2 unpack2(ull v){
    float2 r; asm("mov.b64 {%0, %1}, %2;" : "=f"(r.x), "=f"(r.y) : "l"(v)); return r;
}
__device__ __forceinline__ float sigmoidf_fast(float x){
    return 1.0f / (1.0f + __expf(-x));
}

// ---------------- scratch (static device globals; no allocation) ------------
__device__ float2 g_a[CP][NN][NN];          // a in (cpair, i, k) layout, 134MB
__device__ float2 g_b[CP][NN][NN];          // b in (cpair, j, k) layout, 134MB
__device__ float  g_t[(size_t)NN*NN*CC];    // triangle result, (i,j,c), 134MB
__device__ float  g_sg[(size_t)NN*NN*CC];   // sigmoid(glin) gate, (i,j,c), 134MB

// packed, LN-gain-prescaled weights + per-output-row LN-fold constants
__device__ float2 g_Wp2[128*128];           // proj: 128 dpairs x 128 c
__device__ float2 g_Wg2[128*128];           // gate
__device__ float2 g_Wl2[64*128];            // glin: 64 dpairs
__device__ float2 g_Wo2[64*128];            // out
__device__ float  g_Sp[256], g_Bp[256], g_Sg[256], g_Bg[256];
__device__ float  g_Sl[128], g_Bl[128], g_So[128], g_Bo[128];

// ---------------- prep: weight packing + LN folding constants ---------------
__global__ void prep_kernel(const float* __restrict__ lw, const float* __restrict__ lb,
                            const float* __restrict__ Wp, const float* __restrict__ Wg,
                            const float* __restrict__ cw, const float* __restrict__ cb,
                            const float* __restrict__ Wo, const float* __restrict__ Wl){
    __shared__ float r1[128], r2[128];
    int bid = blockIdx.x;
    int c   = threadIdx.x;
    const float *W, *w, *b;
    float2* W2; float *Sv, *Bv; int d;
    if (bid < 256)      { W = Wp; W2 = g_Wp2; Sv = g_Sp; Bv = g_Bp; w = lw; b = lb; d = bid;       }
    else if (bid < 512) { W = Wg; W2 = g_Wg2; Sv = g_Sg; Bv = g_Bg; w = lw; b = lb; d = bid - 256; }
    else if (bid < 640) { W = Wl; W2 = g_Wl2; Sv = g_Sl; Bv = g_Bl; w = lw; b = lb; d = bid - 512; }
    else                { W = Wo; W2 = g_Wo2; Sv = g_So; Bv = g_Bo; w = cw; b = cb; d = bid - 640; }

    float wv = W[d*128 + c];
    float sw = wv * w[c];
    float sb = wv * b[c];
    ((float*)(W2 + (d >> 1)*128 + c))[d & 1] = sw;   // interleave pair (d, d+1)
    r1[c] = sw; r2[c] = sb;
    __syncthreads();
    for (int s = 64; s > 0; s >>= 1){
        if (c < s){ r1[c] += r1[c+s]; r2[c] += r2[c+s]; }
        __syncthreads();
    }
    if (c == 0){ Sv[d] = r1[0]; Bv[d] = r2[0]; }
}

// ---------------- k1: LN-folded proj/gate/glin, gating, layout transform ----
// smem layout (bytes): xs[128*129]f @0 (66048) | mu[128] @66048 | inv[128] @66560
//                      ws[8192]f2 @67072 (65536) | sgs[8192]f2 @132608 (65536)
#define K1_SMEM 198144

__global__ void __launch_bounds__(256, 1)
k1_kernel(const float* __restrict__ act, const float* __restrict__ mask){
    extern __shared__ char sm[];
    float*  xs    = (float*)sm;                  // transposed act tile [c][pos], pad 129
    float*  mu_s  = (float*)(sm + 66048);
    float*  inv_s = (float*)(sm + 66560);
    float2* ws    = (float2*)(sm + 67072);       // weight chunks (proj @0, gate @4096)
    float2* sgs   = (float2*)(sm + 132608);      // glin-gate staging [pos][64]
    ull* ws_u = (ull*)ws;

    int t   = threadIdx.x;
    int bid = blockIdx.x;
    int i   = bid >> 2;
    int j0  = (bid & 3) * 128;

    // load + transpose act tile: 128 positions x 128 channels
    {
        int pos = t >> 1, ch = (t & 1) * 64;
        const float4* src = (const float4*)(act + ((size_t)(i*NN + j0 + pos))*CC + ch);
        #pragma unroll
        for (int q = 0; q < 16; q++){
            float4 v = src[q];
            int c = ch + q*4;
            xs[(c+0)*129 + pos] = v.x;
            xs[(c+1)*129 + pos] = v.y;
            xs[(c+2)*129 + pos] = v.z;
            xs[(c+3)*129 + pos] = v.w;
        }
    }
    __syncthreads();

    // LN statistics per position
    if (t < 128){
        float s = 0.f, s2 = 0.f;
        #pragma unroll 8
        for (int c = 0; c < 128; c++){ float v = xs[c*129 + t]; s += v; s2 += v*v; }
        float m   = s * (1.f/128.f);
        float var = s2 * (1.f/128.f) - m*m;
        mu_s[t]  = m;
        inv_s[t] = rsqrtf(var + 1e-5f);
    }
    __syncthreads();

    int pg = t >> 5;      // pair group 0..7 (4 pairs each)
    int jg = t & 31;      // position group (4 positions, stride 32)

    // ---- proj + gate: 4 chunks of 32 output-pairs each ----
    for (int ch = 0; ch < 4; ch++){
        for (int u = 0; u < 16; u++){
            int idx = t + u*256;
            ws[idx]        = g_Wp2[ch*4096 + idx];
            ws[4096 + idx] = g_Wg2[ch*4096 + idx];
        }
        __syncthreads();

        ull accP[4][4], accG[4][4];
        #pragma unroll
        for (int q = 0; q < 4; q++)
            #pragma unroll
            for (int pp = 0; pp < 4; pp++){ accP[q][pp] = 0ull; accG[q][pp] = 0ull; }

        #pragma unroll 4
        for (int c = 0; c < 128; c++){
            ull xb[4];
            #pragma unroll
            for (int q = 0; q < 4; q++){
                float xv = xs[c*129 + jg + 32*q];
                xb[q] = pack2(xv, xv);
            }
            #pragma unroll
            for (int pp = 0; pp < 4; pp++){
                ull wp = ws_u[(pg*4 + pp)*128 + c];
                ull wg = ws_u[4096 + (pg*4 + pp)*128 + c];
                #pragma unroll
                for (int q = 0; q < 4; q++){
                    accP[q][pp] = ffma2(xb[q], wp, accP[q][pp]);
                    accG[q][pp] = ffma2(xb[q], wg, accG[q][pp]);
                }
            }
        }

        #pragma unroll
        for (int q = 0; q < 4; q++){
            int pos = jg + 32*q;
            int j   = j0 + pos;
            float mk  = mask[i*NN + j];
            float mui = mu_s[pos], ivi = inv_s[pos];
            #pragma unroll
            for (int pp = 0; pp < 4; pp++){
                int dp = ch*32 + pg*4 + pp, d0 = dp*2;
                float2 aP = unpack2(accP[q][pp]);
                float2 aG = unpack2(accG[q][pp]);
                float p0 = ivi*(aP.x - mui*g_Sp[d0])   + g_Bp[d0];
                float p1 = ivi*(aP.y - mui*g_Sp[d0+1]) + g_Bp[d0+1];
                float q0 = ivi*(aG.x - mui*g_Sg[d0])   + g_Bg[d0];
                float q1 = ivi*(aG.y - mui*g_Sg[d0+1]) + g_Bg[d0+1];
                float2 v = make_float2(p0*mk*sigmoidf_fast(q0), p1*mk*sigmoidf_fast(q1));
                if (dp < 64) g_a[dp][i][j]      = v;
                else         g_b[dp - 64][i][j] = v;
            }
        }
        __syncthreads();
    }

    // ---- glin gate: 2 chunks of 32 output-pairs ----
    for (int ch = 0; ch < 2; ch++){
        for (int u = 0; u < 16; u++){
            int idx = t + u*256;
            ws[idx] = g_Wl2[ch*4096 + idx];
        }
        __syncthreads();

        ull acc[4][4];
        #pragma unroll
        for (int q = 0; q < 4; q++)
            #pragma unroll
            for (int pp = 0; pp < 4; pp++) acc[q][pp] = 0ull;

        #pragma unroll 4
        for (int c = 0; c < 128; c++){
            ull xb[4];
            #pragma unroll
            for (int q = 0; q < 4; q++){
                float xv = xs[c*129 + jg + 32*q];
                xb[q] = pack2(xv, xv);
            }
            #pragma unroll
            for (int pp = 0; pp < 4; pp++){
                ull wl = ws_u[(pg*4 + pp)*128 + c];
                #pragma unroll
                for (int q = 0; q < 4; q++)
                    acc[q][pp] = ffma2(xb[q], wl, acc[q][pp]);
            }
        }

        #pragma unroll
        for (int q = 0; q < 4; q++){
            int pos = jg + 32*q;
            float mui = mu_s[pos], ivi = inv_s[pos];
            #pragma unroll
            for (int pp = 0; pp < 4; pp++){
                int dpl = ch*32 + pg*4 + pp, d0 = dpl*2;
                float2 aa = unpack2(acc[q][pp]);
                float g0 = ivi*(aa.x - mui*g_Sl[d0])   + g_Bl[d0];
                float g1 = ivi*(aa.y - mui*g_Sl[d0+1]) + g_Bl[d0+1];
                sgs[pos*64 + dpl] = make_float2(sigmoidf_fast(g0), sigmoidf_fast(g1));
            }
        }
        __syncthreads();
    }

    // coalesced write of glin gate
    {
        float2* sg2  = (float2*)g_sg;
        size_t  base = (size_t)(i*NN + j0) * 64;
        for (int u = 0; u < 32; u++){
            int idx = t + u*256;
            sg2[base + idx] = sgs[idx];
        }
    }
}

// ---------------- k2: triangle einsum as 64 channel-pair NT-GEMMs -----------
// tile M=128 (i) x N=64 (j), Kblk=16, 128 threads, 8x8 float2 microtile
__global__ void __launch_bounds__(128, 2)
k2_kernel(){
    __shared__ float2 As[16*128];   // k-major [k][row]
    __shared__ float2 Bs[16*64];    // k-major [k][col]
    ull* As_u = (ull*)As;
    ull* Bs_u = (ull*)Bs;

    int cp = blockIdx.z;
    int i0 = blockIdx.y * 128;
    int j0 = blockIdx.x * 64;
    int t  = threadIdx.x;
    int tx = t & 7;       // col base (stride-8 cols)
    int ty = t >> 3;      // row base 0..15 (stride-16 rows)

    const float2* Ag = &g_a[cp][i0][0];
    const float2* Bg = &g_b[cp][j0][0];

    ull acc[8][8];
    #pragma unroll
    for (int a = 0; a < 8; a++)
        #pragma unroll
        for (int b = 0; b < 8; b++) acc[a][b] = 0ull;

    int br  = t & 63;
    int bk0 = (t >> 6) * 8;

    for (int kb = 0; kb < NN; kb += 16){
        const float2* sa = Ag + (size_t)t*NN + kb;
        #pragma unroll
        for (int k = 0; k < 16; k++) As[k*128 + t] = sa[k];
        const float2* sb = Bg + (size_t)br*NN + kb + bk0;
        #pragma unroll
        for (int k = 0; k < 8; k++) Bs[(bk0 + k)*64 + br] = sb[k];
        __syncthreads();

        #pragma unroll
        for (int k = 0; k < 16; k++){
            ull af[8], bf[8];
            #pragma unroll
            for (int o = 0; o < 8; o++) af[o] = As_u[k*128 + ty + 16*o];
            #pragma unroll
            for (int o = 0; o < 8; o++) bf[o] = Bs_u[k*64 + tx + 8*o];
            #pragma unroll
            for (int oi = 0; oi < 8; oi++)
                #pragma unroll
                for (int oj = 0; oj < 8; oj++)
                    acc[oi][oj] = ffma2(af[oi], bf[oj], acc[oi][oj]);
        }
        __syncthreads();
    }

    float2* t2 = (float2*)g_t;
    #pragma unroll
    for (int oi = 0; oi < 8; oi++){
        int ii = i0 + ty + 16*oi;
        #pragma unroll
        for (int oj = 0; oj < 8; oj++){
            int jj = j0 + tx + 8*oj;
            t2[((size_t)ii*NN + jj)*64 + cp] = unpack2(acc[oi][oj]);
        }
    }
}

// ---------------- k3: LN(t) folded + out-GEMM + gate multiply ---------------
// smem: ts[128*129]f @0 | mu @66048 | inv @66560 | ws[4096]f2 @67072 | sgs[8192]f2 @99840
#define K3_SMEM 165376

__global__ void __launch_bounds__(256, 1)
k3_kernel(float* __restrict__ out){
    extern __shared__ char sm[];
    float*  ts    = (float*)sm;
    float*  mu_s  = (float*)(sm + 66048);
    float*  inv_s = (float*)(sm + 66560);
    float2* ws    = (float2*)(sm + 67072);
    float2* sgs   = (float2*)(sm + 99840);   // gate in, output out (in place)
    ull* ws_u = (ull*)ws;

    int t   = threadIdx.x;
    int bid = blockIdx.x;
    int i   = bid >> 2;
    int j0  = (bid & 3) * 128;
    size_t base = (size_t)(i*NN + j0) * 64;

    // load + transpose t tile
    {
        int pos = t >> 1, ch = (t & 1) * 64;
        const float4* src = (const float4*)(g_t + ((size_t)(i*NN + j0 + pos))*CC + ch);
        #pragma unroll
        for (int q = 0; q < 16; q++){
            float4 v = src[q];
            int c = ch + q*4;
            ts[(c+0)*129 + pos] = v.x;
            ts[(c+1)*129 + pos] = v.y;
            ts[(c+2)*129 + pos] = v.z;
            ts[(c+3)*129 + pos] = v.w;
        }
    }
    // load glin gate tile
    {
        const float2* sg2 = (const float2*)g_sg;
        for (int u = 0; u < 32; u++){
            int idx = t + u*256;
            sgs[idx] = sg2[base + idx];
        }
    }
    __syncthreads();

    if (t < 128){
        float s = 0.f, s2 = 0.f;
        #pragma unroll 8
        for (int c = 0; c < 128; c++){ float v = ts[c*129 + t]; s += v; s2 += v*v; }
        float m   = s * (1.f/128.f);
        float var = s2 * (1.f/128.f) - m*m;
        mu_s[t]  = m;
        inv_s[t] = rsqrtf(var + 1e-5f);
    }
    __syncthreads();

    int pg = t >> 5, jg = t & 31;

    for (int ch = 0; ch < 2; ch++){
        for (int u = 0; u < 16; u++){
            int idx = t + u*256;
            ws[idx] = g_Wo2[ch*4096 + idx];
        }
        __syncthreads();

        ull acc[4][4];
        #pragma unroll
        for (int q = 0; q < 4; q++)
            #pragma unroll
            for (int pp = 0; pp < 4; pp++) acc[q][pp] = 0ull;

        #pragma unroll 4
        for (int c = 0; c < 128; c++){
            ull xb[4];
            #pragma unroll
            for (int q = 0; q < 4; q++){
                float xv = ts[c*129 + jg + 32*q];
                xb[q] = pack2(xv, xv);
            }
            #pragma unroll
            for (int pp = 0; pp < 4; pp++){
                ull wo = ws_u[(pg*4 + pp)*128 + c];
                #pragma unroll
                for (int q = 0; q < 4; q++)
                    acc[q][pp] = ffma2(xb[q], wo, acc[q][pp]);
            }
        }

        #pragma unroll
        for (int q = 0; q < 4; q++){
            int pos = jg + 32*q;
            float mui = mu_s[pos], ivi = inv_s[pos];
            #pragma unroll
            for (int pp = 0; pp < 4; pp++){
                int dpl = ch*32 + pg*4 + pp, d0 = dpl*2;
                float2 aa = unpack2(acc[q][pp]);
                float o0 = ivi*(aa.x - mui*g_So[d0])   + g_Bo[d0];
                float o1 = ivi*(aa.y - mui*g_So[d0+1]) + g_Bo[d0+1];
                float2 sg = sgs[pos*64 + dpl];
                sgs[pos*64 + dpl] = make_float2(o0*sg.x, o1*sg.y);
            }
        }
        __syncthreads();
    }

    // coalesced output write
    {
        float2* out2 = (float2*)out;
        for (int u = 0; u < 32; u++){
            int idx = t + u*256;
            out2[base + idx] = sgs[idx];
        }
    }
}

// ---------------- launch -----------------------------------------------------
extern "C" void kernel_launch(void* const* d_in, const int* in_sizes, int n_in,
                              void* d_out, int out_size){
    const float* act  = (const float*)d_in[0];
    const float* mask = (const float*)d_in[1];
    const float* lnw  = (const float*)d_in[2];
    const float* lnb  = (const float*)d_in[3];
    const float* Wp   = (const float*)d_in[4];
    const float* Wg   = (const float*)d_in[5];
    const float* lcw  = (const float*)d_in[6];
    const float* lcb  = (const float*)d_in[7];
    const float* Wo   = (const float*)d_in[8];
    const float* Wl   = (const float*)d_in[9];

    cudaFuncSetAttribute(k1_kernel, cudaFuncAttributeMaxDynamicSharedMemorySize, K1_SMEM);
    cudaFuncSetAttribute(k3_kernel, cudaFuncAttributeMaxDynamicSharedMemorySize, K3_SMEM);

    prep_kernel<<<768, 128>>>(lnw, lnb, Wp, Wg, lcw, lcb, Wo, Wl);
    k1_kernel<<<2048, 256, K1_SMEM>>>(act, mask);
    k2_kernel<<<dim3(8, 4, 64), 128>>>();
    k3_kernel<<<2048, 256, K3_SMEM>>>((float*)d_out);
}

// round 4
// speedup vs baseline: 1.6738x; 1.6738x over previous
#include <cuda_runtime.h>
#include <cstdint>
#include <cstddef>

#define NN 512
#define CC 128
typedef unsigned long long ull;

// ---------------- helpers ----------------------------------------------------
__device__ __forceinline__ ull ffma2(ull a, ull b, ull c){
    ull d; asm("fma.rn.f32x2 %0, %1, %2, %3;" : "=l"(d) : "l"(a), "l"(b), "l"(c)); return d;
}
__device__ __forceinline__ ull pack2(float x, float y){
    ull r; asm("mov.b64 %0, {%1, %2};" : "=l"(r) : "f"(x), "f"(y)); return r;
}
__device__ __forceinline__ float2 unpack2(ull v){
    float2 r; asm("mov.b64 {%0, %1}, %2;" : "=f"(r.x), "=f"(r.y) : "l"(v)); return r;
}
__device__ __forceinline__ float sigmoidf_fast(float x){ return 1.0f/(1.0f+__expf(-x)); }
__device__ __forceinline__ uint32_t f2tf32(float x){
    uint32_t r; asm("cvt.rna.tf32.f32 %0, %1;" : "=r"(r) : "f"(x)); return r;
}
__device__ __forceinline__ void mma_tf32(float* d, const uint32_t* a, const uint32_t* b){
    asm volatile("mma.sync.aligned.m16n8k8.row.col.f32.tf32.tf32.f32 "
        "{%0,%1,%2,%3}, {%4,%5,%6,%7}, {%8,%9}, {%0,%1,%2,%3};"
        : "+f"(d[0]), "+f"(d[1]), "+f"(d[2]), "+f"(d[3])
        : "r"(a[0]), "r"(a[1]), "r"(a[2]), "r"(a[3]), "r"(b[0]), "r"(b[1]));
}

// ---------------- scratch ----------------------------------------------------
__device__ float g_a[(size_t)CC*NN*NN];     // per-channel planes [c][i][k]
__device__ float g_b[(size_t)CC*NN*NN];     // per-channel planes [c][j][k]
__device__ float g_t[(size_t)CC*NN*NN];     // triangle result planes [c][i][j]
__device__ float g_sg[(size_t)NN*NN*CC];    // sigmoid(glin), (i,j,cpair-f2) layout

__device__ float2 g_Wp2[128*128];
__device__ float2 g_Wg2[128*128];
__device__ float2 g_Wl2[64*128];
__device__ float2 g_Wo2[64*128];
__device__ float  g_Sp[256], g_Bp[256], g_Sg[256], g_Bg[256];
__device__ float  g_Sl[128], g_Bl[128], g_So[128], g_Bo[128];

// ---------------- prep -------------------------------------------------------
__global__ void prep_kernel(const float* __restrict__ lw, const float* __restrict__ lb,
                            const float* __restrict__ Wp, const float* __restrict__ Wg,
                            const float* __restrict__ cw, const float* __restrict__ cb,
                            const float* __restrict__ Wo, const float* __restrict__ Wl){
    __shared__ float r1[128], r2[128];
    int bid = blockIdx.x;
    int c   = threadIdx.x;
    const float *W, *w, *b;
    float2* W2; float *Sv, *Bv; int d;
    if (bid < 256)      { W = Wp; W2 = g_Wp2; Sv = g_Sp; Bv = g_Bp; w = lw; b = lb; d = bid;       }
    else if (bid < 512) { W = Wg; W2 = g_Wg2; Sv = g_Sg; Bv = g_Bg; w = lw; b = lb; d = bid - 256; }
    else if (bid < 640) { W = Wl; W2 = g_Wl2; Sv = g_Sl; Bv = g_Bl; w = lw; b = lb; d = bid - 512; }
    else                { W = Wo; W2 = g_Wo2; Sv = g_So; Bv = g_Bo; w = cw; b = cb; d = bid - 640; }

    float wv = W[d*128 + c];
    float sw = wv * w[c];
    float sb = wv * b[c];
    ((float*)(W2 + (d >> 1)*128 + c))[d & 1] = sw;
    r1[c] = sw; r2[c] = sb;
    __syncthreads();
    for (int s = 64; s > 0; s >>= 1){
        if (c < s){ r1[c] += r1[c+s]; r2[c] += r2[c+s]; }
        __syncthreads();
    }
    if (c == 0){ Sv[d] = r1[0]; Bv[d] = r2[0]; }
}

// ---------------- k1: LN-folded proj/gate/glin (j-tile 64, 2 CTAs/SM) --------
// smem: xs[128*65]f (33280) | mu[64] @33280 | inv[64] @33536 |
//       ws f2[4096] @33792 (32768) | sgs f2[64*65] @66560 (33280)  => 99840
#define K1_SMEM 99840

__global__ void __launch_bounds__(256, 2)
k1_kernel(const float* __restrict__ act, const float* __restrict__ mask){
    extern __shared__ char sm[];
    float*  xs    = (float*)sm;                  // [c][pos] stride 65
    float*  mu_s  = (float*)(sm + 33280);
    float*  inv_s = (float*)(sm + 33536);
    float2* ws    = (float2*)(sm + 33792);
    float2* sgs   = (float2*)(sm + 66560);       // [pos][dpl] stride 65
    ull* ws_u = (ull*)ws;

    int t   = threadIdx.x;
    int bid = blockIdx.x;
    int i   = bid >> 3;
    int j0  = (bid & 7) * 64;
    const size_t plane = (size_t)NN*NN;

    #pragma unroll
    for (int u = 0; u < 8; u++){
        int idx = t + u*256;
        int pos = idx >> 5, f4 = idx & 31;
        float4 v = *(const float4*)(act + ((size_t)(i*NN + j0 + pos))*CC + f4*4);
        int c = f4*4;
        xs[(c+0)*65 + pos] = v.x;
        xs[(c+1)*65 + pos] = v.y;
        xs[(c+2)*65 + pos] = v.z;
        xs[(c+3)*65 + pos] = v.w;
    }
    __syncthreads();

    if (t < 64){
        float s = 0.f, s2 = 0.f;
        #pragma unroll 8
        for (int c = 0; c < 128; c++){ float v = xs[c*65 + t]; s += v; s2 += v*v; }
        float m   = s * (1.f/128.f);
        float var = s2 * (1.f/128.f) - m*m;
        mu_s[t]  = m;
        inv_s[t] = rsqrtf(var + 1e-5f);
    }
    __syncthreads();

    int jg = t & 15;
    int pg = t >> 4;

    for (int ch = 0; ch < 4; ch++){
        #pragma unroll
        for (int u = 0; u < 16; u++){ int idx = t + u*256; ws[idx] = g_Wp2[ch*4096 + idx]; }
        __syncthreads();

        ull accP[4][2];
        #pragma unroll
        for (int q = 0; q < 4; q++){ accP[q][0] = 0ull; accP[q][1] = 0ull; }
        #pragma unroll 4
        for (int c = 0; c < 128; c++){
            ull xb[4];
            #pragma unroll
            for (int q = 0; q < 4; q++){ float xv = xs[c*65 + jg + 16*q]; xb[q] = pack2(xv, xv); }
            #pragma unroll
            for (int pp = 0; pp < 2; pp++){
                ull w = ws_u[(pg*2 + pp)*128 + c];
                #pragma unroll
                for (int q = 0; q < 4; q++) accP[q][pp] = ffma2(xb[q], w, accP[q][pp]);
            }
        }
        __syncthreads();

        #pragma unroll
        for (int u = 0; u < 16; u++){ int idx = t + u*256; ws[idx] = g_Wg2[ch*4096 + idx]; }
        __syncthreads();

        ull accG[4][2];
        #pragma unroll
        for (int q = 0; q < 4; q++){ accG[q][0] = 0ull; accG[q][1] = 0ull; }
        #pragma unroll 4
        for (int c = 0; c < 128; c++){
            ull xb[4];
            #pragma unroll
            for (int q = 0; q < 4; q++){ float xv = xs[c*65 + jg + 16*q]; xb[q] = pack2(xv, xv); }
            #pragma unroll
            for (int pp = 0; pp < 2; pp++){
                ull w = ws_u[(pg*2 + pp)*128 + c];
                #pragma unroll
                for (int q = 0; q < 4; q++) accG[q][pp] = ffma2(xb[q], w, accG[q][pp]);
            }
        }
        __syncthreads();

        #pragma unroll
        for (int q = 0; q < 4; q++){
            int pos = jg + 16*q;
            int j   = j0 + pos;
            float mk  = mask[(size_t)i*NN + j];
            float mui = mu_s[pos], ivi = inv_s[pos];
            #pragma unroll
            for (int pp = 0; pp < 2; pp++){
                int dp = ch*32 + pg*2 + pp, d0 = dp*2;
                float2 aP = unpack2(accP[q][pp]);
                float2 aG = unpack2(accG[q][pp]);
                float p0 = ivi*(aP.x - mui*g_Sp[d0])   + g_Bp[d0];
                float p1 = ivi*(aP.y - mui*g_Sp[d0+1]) + g_Bp[d0+1];
                float q0 = ivi*(aG.x - mui*g_Sg[d0])   + g_Bg[d0];
                float q1 = ivi*(aG.y - mui*g_Sg[d0+1]) + g_Bg[d0+1];
                float va = p0*mk*sigmoidf_fast(q0);
                float vb = p1*mk*sigmoidf_fast(q1);
                if (dp < 64){
                    g_a[(size_t)(2*dp  )*plane + (size_t)i*NN + j] = va;
                    g_a[(size_t)(2*dp+1)*plane + (size_t)i*NN + j] = vb;
                } else {
                    int e0 = 2*(dp - 64);
                    g_b[(size_t)(e0  )*plane + (size_t)i*NN + j] = va;
                    g_b[(size_t)(e0+1)*plane + (size_t)i*NN + j] = vb;
                }
            }
        }
    }

    for (int ch = 0; ch < 2; ch++){
        __syncthreads();
        #pragma unroll
        for (int u = 0; u < 16; u++){ int idx = t + u*256; ws[idx] = g_Wl2[ch*4096 + idx]; }
        __syncthreads();

        ull acc[4][2];
        #pragma unroll
        for (int q = 0; q < 4; q++){ acc[q][0] = 0ull; acc[q][1] = 0ull; }
        #pragma unroll 4
        for (int c = 0; c < 128; c++){
            ull xb[4];
            #pragma unroll
            for (int q = 0; q < 4; q++){ float xv = xs[c*65 + jg + 16*q]; xb[q] = pack2(xv, xv); }
            #pragma unroll
            for (int pp = 0; pp < 2; pp++){
                ull w = ws_u[(pg*2 + pp)*128 + c];
                #pragma unroll
                for (int q = 0; q < 4; q++) acc[q][pp] = ffma2(xb[q], w, acc[q][pp]);
            }
        }

        #pragma unroll
        for (int q = 0; q < 4; q++){
            int pos = jg + 16*q;
            float mui = mu_s[pos], ivi = inv_s[pos];
            #pragma unroll
            for (int pp = 0; pp < 2; pp++){
                int dpl = ch*32 + pg*2 + pp, d0 = dpl*2;
                float2 aa = unpack2(acc[q][pp]);
                float g0 = ivi*(aa.x - mui*g_Sl[d0])   + g_Bl[d0];
                float g1 = ivi*(aa.y - mui*g_Sl[d0+1]) + g_Bl[d0+1];
                sgs[pos*65 + dpl] = make_float2(sigmoidf_fast(g0), sigmoidf_fast(g1));
            }
        }
    }
    __syncthreads();

    {
        float2* sg2  = (float2*)g_sg;
        size_t  base = (size_t)(i*NN + j0) * 64;
        #pragma unroll
        for (int u = 0; u < 16; u++){
            int g   = t + u*256;
            int pos = g >> 6, dpl = g & 63;
            sg2[base + g] = sgs[pos*65 + dpl];
        }
    }
}

// ---------------- k2: triangle as 128 per-channel TF32 mma.sync GEMMs --------
// block tile 128x128, K-chunk 32, double-buffered smem rows stride 36
#define K2_LDA 36
#define K2_BUF (128*K2_LDA)          // uint32 elems per buffer = 4608 (18432 B)
#define K2_SMEM (4*K2_BUF*4)         // 73728 B

__global__ void __launch_bounds__(256, 1)
k2_kernel(){
    extern __shared__ uint32_t smw[];
    // layout: A0 | B0 | A1 | B1
    int t   = threadIdx.x;
    int wid = t >> 5, lane = t & 31;
    int g   = lane >> 2, t4 = lane & 3;
    int WM  = (wid >> 2) * 64;       // warp m offset
    int WN  = (wid & 3) * 32;        // warp n offset

    int c  = blockIdx.z;
    int i0 = blockIdx.y * 128;
    int j0 = blockIdx.x * 128;
    const size_t plane = (size_t)NN*NN;
    const float* Ap = g_a + (size_t)c*plane + (size_t)i0*NN;
    const float* Bp = g_b + (size_t)c*plane + (size_t)j0*NN;

    // staging: each thread covers 4 float4 per matrix per chunk
    // (2 threads per row x 4 f4 each = 8 f4 = 32 floats = full K-chunk row)
    int srow = t >> 1;               // 0..127
    int sf4  = (t & 1) * 4;          // f4 col base: 0 or 4

    float acc[4][4][4];
    #pragma unroll
    for (int mi = 0; mi < 4; mi++)
        #pragma unroll
        for (int ni = 0; ni < 4; ni++)
            #pragma unroll
            for (int r = 0; r < 4; r++) acc[mi][ni][r] = 0.f;

    float4 pa[4], pb[4];
    // prefetch chunk 0
    #pragma unroll
    for (int u = 0; u < 4; u++){
        pa[u] = *(const float4*)(Ap + (size_t)srow*NN + (sf4 + u)*4);
        pb[u] = *(const float4*)(Bp + (size_t)srow*NN + (sf4 + u)*4);
    }

    for (int kb = 0; kb < 16; kb++){
        uint32_t* As = smw + (kb & 1) * 2 * K2_BUF;
        uint32_t* Bs = As + K2_BUF;
        // store prefetched chunk (convert to tf32 during staging)
        #pragma unroll
        for (int u = 0; u < 4; u++){
            int cb = (sf4 + u)*4;
            uint32_t* da = As + srow*K2_LDA + cb;
            da[0] = f2tf32(pa[u].x); da[1] = f2tf32(pa[u].y);
            da[2] = f2tf32(pa[u].z); da[3] = f2tf32(pa[u].w);
            uint32_t* db = Bs + srow*K2_LDA + cb;
            db[0] = f2tf32(pb[u].x); db[1] = f2tf32(pb[u].y);
            db[2] = f2tf32(pb[u].z); db[3] = f2tf32(pb[u].w);
        }
        __syncthreads();

        // prefetch next chunk while computing
        if (kb < 15){
            int k0 = (kb + 1) * 32;
            #pragma unroll
            for (int u = 0; u < 4; u++){
                pa[u] = *(const float4*)(Ap + (size_t)srow*NN + k0 + (sf4 + u)*4);
                pb[u] = *(const float4*)(Bp + (size_t)srow*NN + k0 + (sf4 + u)*4);
            }
        }

        #pragma unroll
        for (int k8 = 0; k8 < 4; k8++){
            int kof = k8*8 + t4;
            uint32_t af[4][4];
            #pragma unroll
            for (int mi = 0; mi < 4; mi++){
                const uint32_t* pA = As + (WM + mi*16 + g)*K2_LDA + kof;
                af[mi][0] = pA[0];
                af[mi][1] = pA[8*K2_LDA];
                af[mi][2] = pA[4];
                af[mi][3] = pA[8*K2_LDA + 4];
            }
            #pragma unroll
            for (int ni = 0; ni < 4; ni++){
                const uint32_t* pB = Bs + (WN + ni*8 + g)*K2_LDA + kof;
                uint32_t bf[2];
                bf[0] = pB[0];
                bf[1] = pB[4];
                #pragma unroll
                for (int mi = 0; mi < 4; mi++)
                    mma_tf32(acc[mi][ni], af[mi], bf);
            }
        }
        __syncthreads();
    }

    // epilogue: write g_t[c][i][j]
    float* Tp = g_t + (size_t)c*plane;
    #pragma unroll
    for (int mi = 0; mi < 4; mi++){
        int r0 = i0 + WM + mi*16 + g;
        #pragma unroll
        for (int ni = 0; ni < 4; ni++){
            int cc = j0 + WN + ni*8 + 2*t4;
            *(float2*)(Tp + (size_t)r0*NN + cc)     = make_float2(acc[mi][ni][0], acc[mi][ni][1]);
            *(float2*)(Tp + (size_t)(r0+8)*NN + cc) = make_float2(acc[mi][ni][2], acc[mi][ni][3]);
        }
    }
}

// ---------------- k3: LN(t) folded + out-GEMM + gate (j-tile 64) -------------
// smem: ts[128*68]f (34816) | mu @34816 | inv @35072 |
//       ws f2[4096] @35328 (32768) | sgs f2[64*65] @68096 (33280) => 101376
#define K3_SMEM 101376

__global__ void __launch_bounds__(256, 2)
k3_kernel(float* __restrict__ out){
    extern __shared__ char sm[];
    float*  ts    = (float*)sm;
    float*  mu_s  = (float*)(sm + 34816);
    float*  inv_s = (float*)(sm + 35072);
    float2* ws    = (float2*)(sm + 35328);
    float2* sgs   = (float2*)(sm + 68096);
    ull* ws_u = (ull*)ws;

    int t   = threadIdx.x;
    int bid = blockIdx.x;
    int i   = bid >> 3;
    int j0  = (bid & 7) * 64;
    const size_t plane = (size_t)NN*NN;
    size_t base = (size_t)(i*NN + j0) * 64;

    #pragma unroll
    for (int u = 0; u < 8; u++){
        int idx = t + u*256;
        int c = idx >> 4, f4 = idx & 15;
        float4 v = *(const float4*)(g_t + ((size_t)c*NN + i)*NN + j0 + f4*4);
        *(float4*)&ts[c*68 + f4*4] = v;
    }
    {
        const float2* sg2 = (const float2*)g_sg;
        #pragma unroll
        for (int u = 0; u < 16; u++){
            int g   = t + u*256;
            int pos = g >> 6, dpl = g & 63;
            sgs[pos*65 + dpl] = sg2[base + g];
        }
    }
    __syncthreads();

    if (t < 64){
        float s = 0.f, s2 = 0.f;
        #pragma unroll 8
        for (int c = 0; c < 128; c++){ float v = ts[c*68 + t]; s += v; s2 += v*v; }
        float m   = s * (1.f/128.f);
        float var = s2 * (1.f/128.f) - m*m;
        mu_s[t]  = m;
        inv_s[t] = rsqrtf(var + 1e-5f);
    }
    __syncthreads();

    int jg = t & 15, pg = t >> 4;

    for (int ch = 0; ch < 2; ch++){
        #pragma unroll
        for (int u = 0; u < 16; u++){ int idx = t + u*256; ws[idx] = g_Wo2[ch*4096 + idx]; }
        __syncthreads();

        ull acc[4][2];
        #pragma unroll
        for (int q = 0; q < 4; q++){ acc[q][0] = 0ull; acc[q][1] = 0ull; }
        #pragma unroll 4
        for (int c = 0; c < 128; c++){
            ull xb[4];
            #pragma unroll
            for (int q = 0; q < 4; q++){ float xv = ts[c*68 + jg + 16*q]; xb[q] = pack2(xv, xv); }
            #pragma unroll
            for (int pp = 0; pp < 2; pp++){
                ull w = ws_u[(pg*2 + pp)*128 + c];
                #pragma unroll
                for (int q = 0; q < 4; q++) acc[q][pp] = ffma2(xb[q], w, acc[q][pp]);
            }
        }

        #pragma unroll
        for (int q = 0; q < 4; q++){
            int pos = jg + 16*q;
            float mui = mu_s[pos], ivi = inv_s[pos];
            #pragma unroll
            for (int pp = 0; pp < 2; pp++){
                int dpl = ch*32 + pg*2 + pp, d0 = dpl*2;
                float2 aa = unpack2(acc[q][pp]);
                float o0 = ivi*(aa.x - mui*g_So[d0])   + g_Bo[d0];
                float o1 = ivi*(aa.y - mui*g_So[d0+1]) + g_Bo[d0+1];
                float2 sg = sgs[pos*65 + dpl];
                sgs[pos*65 + dpl] = make_float2(o0*sg.x, o1*sg.y);
            }
        }
        __syncthreads();
    }

    {
        float2* out2 = (float2*)out;
        #pragma unroll
        for (int u = 0; u < 16; u++){
            int g   = t + u*256;
            int pos = g >> 6, dpl = g & 63;
            out2[base + g] = sgs[pos*65 + dpl];
        }
    }
}

// ---------------- launch -----------------------------------------------------
extern "C" void kernel_launch(void* const* d_in, const int* in_sizes, int n_in,
                              void* d_out, int out_size){
    const float* act  = (const float*)d_in[0];
    const float* mask = (const float*)d_in[1];
    const float* lnw  = (const float*)d_in[2];
    const float* lnb  = (const float*)d_in[3];
    const float* Wp   = (const float*)d_in[4];
    const float* Wg   = (const float*)d_in[5];
    const float* lcw  = (const float*)d_in[6];
    const float* lcb  = (const float*)d_in[7];
    const float* Wo   = (const float*)d_in[8];
    const float* Wl   = (const float*)d_in[9];

    cudaFuncSetAttribute(k1_kernel, cudaFuncAttributeMaxDynamicSharedMemorySize, K1_SMEM);
    cudaFuncSetAttribute(k2_kernel, cudaFuncAttributeMaxDynamicSharedMemorySize, K2_SMEM);
    cudaFuncSetAttribute(k3_kernel, cudaFuncAttributeMaxDynamicSharedMemorySize, K3_SMEM);

    prep_kernel<<<768, 128>>>(lnw, lnb, Wp, Wg, lcw, lcb, Wo, Wl);
    k1_kernel<<<4096, 256, K1_SMEM>>>(act, mask);
    k2_kernel<<<dim3(4, 4, 128), 256, K2_SMEM>>>();
    k3_kernel<<<4096, 256, K3_SMEM>>>((float*)d_out);
}

// round 5
// speedup vs baseline: 2.4283x; 1.4507x over previous
#include <cuda_runtime.h>
#include <cstdint>
#include <cstddef>

#define NN 512
#define CC 128
typedef unsigned long long ull;
static const size_t PLANE = (size_t)NN * NN;

// ---------------- helpers ----------------------------------------------------
__device__ __forceinline__ ull ffma2(ull a, ull b, ull c){
    ull d; asm("fma.rn.f32x2 %0, %1, %2, %3;" : "=l"(d) : "l"(a), "l"(b), "l"(c)); return d;
}
__device__ __forceinline__ ull pack2(float x, float y){
    ull r; asm("mov.b64 %0, {%1, %2};" : "=l"(r) : "f"(x), "f"(y)); return r;
}
__device__ __forceinline__ float2 unpack2(ull v){
    float2 r; asm("mov.b64 {%0, %1}, %2;" : "=f"(r.x), "=f"(r.y) : "l"(v)); return r;
}
__device__ __forceinline__ float sigmoidf_fast(float x){ return 1.0f/(1.0f+__expf(-x)); }
__device__ __forceinline__ uint32_t f2tf32(float x){
    uint32_t r; asm("cvt.rna.tf32.f32 %0, %1;" : "=r"(r) : "f"(x)); return r;
}
__device__ __forceinline__ float tf32r(float x){ return __uint_as_float(f2tf32(x)); }
__device__ __forceinline__ void mma_tf32(float* d, const uint32_t* a, const uint32_t* b){
    asm volatile("mma.sync.aligned.m16n8k8.row.col.f32.tf32.tf32.f32 "
        "{%0,%1,%2,%3}, {%4,%5,%6,%7}, {%8,%9}, {%0,%1,%2,%3};"
        : "+f"(d[0]), "+f"(d[1]), "+f"(d[2]), "+f"(d[3])
        : "r"(a[0]), "r"(a[1]), "r"(a[2]), "r"(a[3]), "r"(b[0]), "r"(b[1]));
}
__device__ __forceinline__ uint32_t smem_u32(const void* p){
    uint32_t a; asm("{ .reg .u64 t; cvta.to.shared.u64 t, %1; cvt.u32.u64 %0, t; }" : "=r"(a) : "l"(p)); return a;
}
__device__ __forceinline__ void cp16(uint32_t dst, const void* src){
    asm volatile("cp.async.cg.shared.global [%0], [%1], 16;" :: "r"(dst), "l"(src) : "memory");
}
__device__ __forceinline__ void cp_commit(){ asm volatile("cp.async.commit_group;" ::: "memory"); }
template<int N> __device__ __forceinline__ void cp_wait(){
    asm volatile("cp.async.wait_group %0;" :: "n"(N) : "memory");
}

// ---------------- scratch ----------------------------------------------------
__device__ float g_x [(size_t)CC*NN*NN];    // tf32-rounded act, (pos, c)
__device__ float g_mu [NN*NN];
__device__ float g_inv[NN*NN];
__device__ float g_a[(size_t)CC*NN*NN];     // per-channel planes [c][pos] (tf32-rounded)
__device__ float g_b[(size_t)CC*NN*NN];
__device__ float g_t[(size_t)CC*NN*NN];     // triangle result planes [c][i][j] fp32
__device__ float g_sg[(size_t)NN*NN*CC];    // sigmoid(glin), (pos, d) fp32

__device__ float  g_Wc[2][256*128];         // [y][proj128;gate128][c] tf32-rounded
__device__ float  g_Wlr[128*128];           // glin tf32-rounded
__device__ float2 g_Wo2[64*128];            // out weights fp32, pair-interleaved (k3)
__device__ float  g_Sp[256], g_Bp[256], g_Sg[256], g_Bg[256];
__device__ float  g_Sl[128], g_Bl[128], g_So[128], g_Bo[128];

// ---------------- k0: LN stats + tf32-rounded act copy -----------------------
__global__ void k0_kernel(const float* __restrict__ act){
    int pos  = blockIdx.x*8 + (threadIdx.x >> 5);
    int lane = threadIdx.x & 31;
    const float4 v = ((const float4*)act)[(size_t)pos*32 + lane];
    float s  = v.x + v.y + v.z + v.w;
    float s2 = v.x*v.x + v.y*v.y + v.z*v.z + v.w*v.w;
    #pragma unroll
    for (int o = 16; o; o >>= 1){
        s  += __shfl_xor_sync(0xffffffffu, s,  o);
        s2 += __shfl_xor_sync(0xffffffffu, s2, o);
    }
    float m   = s * (1.f/128.f);
    float var = s2 * (1.f/128.f) - m*m;
    float4 r = make_float4(tf32r(v.x), tf32r(v.y), tf32r(v.z), tf32r(v.w));
    ((float4*)g_x)[(size_t)pos*32 + lane] = r;
    if (lane == 0){ g_mu[pos] = m; g_inv[pos] = rsqrtf(var + 1e-5f); }
}

// ---------------- prep -------------------------------------------------------
__global__ void prep_kernel(const float* __restrict__ lw, const float* __restrict__ lb,
                            const float* __restrict__ Wp, const float* __restrict__ Wg,
                            const float* __restrict__ cw, const float* __restrict__ cb,
                            const float* __restrict__ Wo, const float* __restrict__ Wl){
    __shared__ float r1[128], r2[128];
    int bid = blockIdx.x;
    int c   = threadIdx.x;
    float sv = 0.f, bv = 0.f;
    float *Sv = nullptr, *Bv = nullptr; int d = 0;

    if (bid < 256){            // proj
        d = bid;
        float sw = Wp[d*128 + c] * lw[c];
        float sr = tf32r(sw);
        g_Wc[d>>7][(d & 127)*128 + c] = sr;
        sv = sr; bv = Wp[d*128 + c] * lb[c];
        Sv = g_Sp; Bv = g_Bp;
    } else if (bid < 512){     // gate
        d = bid - 256;
        float sw = Wg[d*128 + c] * lw[c];
        float sr = tf32r(sw);
        g_Wc[d>>7][(128 + (d & 127))*128 + c] = sr;
        sv = sr; bv = Wg[d*128 + c] * lb[c];
        Sv = g_Sg; Bv = g_Bg;
    } else if (bid < 640){     // glin
        d = bid - 512;
        float sw = Wl[d*128 + c] * lw[c];
        float sr = tf32r(sw);
        g_Wlr[d*128 + c] = sr;
        sv = sr; bv = Wl[d*128 + c] * lb[c];
        Sv = g_Sl; Bv = g_Bl;
    } else {                   // out (fp32, for k3)
        d = bid - 640;
        float sw = Wo[d*128 + c] * cw[c];
        ((float*)(g_Wo2 + (d >> 1)*128 + c))[d & 1] = sw;
        sv = sw; bv = Wo[d*128 + c] * cb[c];
        Sv = g_So; Bv = g_Bo;
    }
    r1[c] = sv; r2[c] = bv;
    __syncthreads();
    for (int s = 64; s > 0; s >>= 1){
        if (c < s){ r1[c] += r1[c+s]; r2[c] += r2[c+s]; }
        __syncthreads();
    }
    if (c == 0){ Sv[d] = r1[0]; Bv[d] = r2[0]; }
}

// ---------------- k1pg: proj+gate via tf32 mma, LN-folded --------------------
// smem: A[2][128*36] @0 (36864) | B[2][256*36] @36864 (73728) |
//       smu@110592 sinv@111104 cS1@111616 cB1@112128 cS2@112640 cB2@113152 smk@113664
#define K1PG_SMEM 114176

__global__ void __launch_bounds__(256, 1)
k1pg_kernel(const float* __restrict__ mask){
    extern __shared__ char sm[];
    float* smu  = (float*)(sm + 110592);
    float* sinv = (float*)(sm + 111104);
    float* cS1  = (float*)(sm + 111616);
    float* cB1  = (float*)(sm + 112128);
    float* cS2  = (float*)(sm + 112640);
    float* cB2  = (float*)(sm + 113152);
    float* smk  = (float*)(sm + 113664);
    uint32_t sbase = smem_u32(sm);

    int t = threadIdx.x, wid = t >> 5, lane = t & 31;
    int g = lane >> 2, t4 = lane & 3;
    int WM = (wid >> 2) * 64, WN = (wid & 3) * 32;
    int m0 = blockIdx.x * 128;
    int y  = blockIdx.y;

    if (t < 128){
        smu[t]  = g_mu[m0 + t];
        sinv[t] = g_inv[m0 + t];
        smk[t]  = mask[m0 + t];
        int d   = y*128 + t;
        cS1[t] = g_Sp[d]; cB1[t] = g_Bp[d];
        cS2[t] = g_Sg[d]; cB2[t] = g_Bg[d];
    }

    const float* Asrc = g_x + (size_t)m0 * 128;
    const float* Bsrc = &g_Wc[y][0];

    int srow = t >> 1, sf4 = (t & 1) * 4;

    // chunk loader: A 128x32, B 256x32
    #define K1_LOAD(kb, buf) do {                                              \
        uint32_t adst = sbase + ((buf)*4608 + srow*36)*4;                      \
        const float* asp = Asrc + (size_t)srow*128 + (kb)*32;                  \
        _Pragma("unroll")                                                      \
        for (int u = 0; u < 4; u++) cp16(adst + (sf4+u)*16, asp + (sf4+u)*4);  \
        uint32_t bdst = sbase + 36864 + ((buf)*9216 + t*36)*4;                 \
        const float* bsp = Bsrc + (size_t)t*128 + (kb)*32;                     \
        _Pragma("unroll")                                                      \
        for (int u = 0; u < 8; u++) cp16(bdst + u*16, bsp + u*4);              \
    } while(0)

    float accP[4][4][4], accG[4][4][4];
    #pragma unroll
    for (int mi = 0; mi < 4; mi++)
        #pragma unroll
        for (int ni = 0; ni < 4; ni++)
            #pragma unroll
            for (int r = 0; r < 4; r++){ accP[mi][ni][r] = 0.f; accG[mi][ni][r] = 0.f; }

    K1_LOAD(0, 0); cp_commit();

    #pragma unroll
    for (int kb = 0; kb < 4; kb++){
        if (kb < 3){ K1_LOAD(kb+1, (kb+1)&1); cp_commit(); }
        if (kb < 3) cp_wait<1>(); else cp_wait<0>();
        __syncthreads();
        const uint32_t* Au = (const uint32_t*)sm + (kb&1)*4608;
        const uint32_t* Bu = (const uint32_t*)(sm + 36864) + (kb&1)*9216;
        #pragma unroll
        for (int k8 = 0; k8 < 4; k8++){
            int kof = k8*8 + t4;
            uint32_t af[4][4];
            #pragma unroll
            for (int mi = 0; mi < 4; mi++){
                int base = (WM + mi*16 + g)*36 + kof;
                af[mi][0] = Au[base];         af[mi][1] = Au[base + 8*36];
                af[mi][2] = Au[base + 4];     af[mi][3] = Au[base + 8*36 + 4];
            }
            #pragma unroll
            for (int ni = 0; ni < 4; ni++){
                int bbP = (WN + ni*8 + g)*36 + kof;
                int bbG = bbP + 128*36;
                uint32_t bfP[2] = { Bu[bbP], Bu[bbP + 4] };
                uint32_t bfG[2] = { Bu[bbG], Bu[bbG + 4] };
                #pragma unroll
                for (int mi = 0; mi < 4; mi++){
                    mma_tf32(accP[mi][ni], af[mi], bfP);
                    mma_tf32(accG[mi][ni], af[mi], bfG);
                }
            }
        }
        __syncthreads();
    }
    #undef K1_LOAD

    // epilogue: LN-fold + mask*sigmoid(gate), tf32-rounded store to planes
    float* dst = (y == 0) ? g_a : g_b;
    #pragma unroll
    for (int mi = 0; mi < 4; mi++){
        int m = WM + mi*16 + g;
        size_t pos0 = (size_t)(m0 + m), pos1 = pos0 + 8;
        float mu0 = smu[m],   iv0 = sinv[m],   mk0 = smk[m];
        float mu1 = smu[m+8], iv1 = sinv[m+8], mk1 = smk[m+8];
        #pragma unroll
        for (int ni = 0; ni < 4; ni++){
            int dl = WN + ni*8 + 2*t4, dl1 = dl + 1;
            float S0 = cS1[dl], S1 = cS1[dl1], B0 = cB1[dl], B1 = cB1[dl1];
            float G0 = cS2[dl], G1 = cS2[dl1], H0 = cB2[dl], H1 = cB2[dl1];
            float p00 = iv0*(accP[mi][ni][0] - mu0*S0) + B0;
            float p01 = iv0*(accP[mi][ni][1] - mu0*S1) + B1;
            float p10 = iv1*(accP[mi][ni][2] - mu1*S0) + B0;
            float p11 = iv1*(accP[mi][ni][3] - mu1*S1) + B1;
            float q00 = iv0*(accG[mi][ni][0] - mu0*G0) + H0;
            float q01 = iv0*(accG[mi][ni][1] - mu0*G1) + H1;
            float q10 = iv1*(accG[mi][ni][2] - mu1*G0) + H0;
            float q11 = iv1*(accG[mi][ni][3] - mu1*G1) + H1;
            dst[(size_t)dl *PLANE + pos0] = tf32r(p00*mk0*sigmoidf_fast(q00));
            dst[(size_t)dl1*PLANE + pos0] = tf32r(p01*mk0*sigmoidf_fast(q01));
            dst[(size_t)dl *PLANE + pos1] = tf32r(p10*mk1*sigmoidf_fast(q10));
            dst[(size_t)dl1*PLANE + pos1] = tf32r(p11*mk1*sigmoidf_fast(q11));
        }
    }
}

// ---------------- k1gl: glin gate via tf32 mma -------------------------------
// smem: A[2][128*36] @0 | B[2][128*36] @36864 | smu@73728 sinv@74240
//       cS1@74752 cB1@75264 | sgs[128*130] @75776 (66560) => 142336
#define K1GL_SMEM 142336

__global__ void __launch_bounds__(256, 1)
k1gl_kernel(){
    extern __shared__ char sm[];
    float* smu  = (float*)(sm + 73728);
    float* sinv = (float*)(sm + 74240);
    float* cS1  = (float*)(sm + 74752);
    float* cB1  = (float*)(sm + 75264);
    float* sgs  = (float*)(sm + 75776);
    uint32_t sbase = smem_u32(sm);

    int t = threadIdx.x, wid = t >> 5, lane = t & 31;
    int g = lane >> 2, t4 = lane & 3;
    int WM = (wid >> 2) * 64, WN = (wid & 3) * 32;
    int m0 = blockIdx.x * 128;

    if (t < 128){
        smu[t]  = g_mu[m0 + t];
        sinv[t] = g_inv[m0 + t];
        cS1[t] = g_Sl[t]; cB1[t] = g_Bl[t];
    }

    const float* Asrc = g_x + (size_t)m0 * 128;
    int srow = t >> 1, sf4 = (t & 1) * 4;

    #define K1G_LOAD(kb, buf) do {                                             \
        uint32_t adst = sbase + ((buf)*4608 + srow*36)*4;                      \
        const float* asp = Asrc + (size_t)srow*128 + (kb)*32;                  \
        _Pragma("unroll")                                                      \
        for (int u = 0; u < 4; u++) cp16(adst + (sf4+u)*16, asp + (sf4+u)*4);  \
        uint32_t bdst = sbase + 36864 + ((buf)*4608 + srow*36)*4;              \
        const float* bsp = g_Wlr + (size_t)srow*128 + (kb)*32;                 \
        _Pragma("unroll")                                                      \
        for (int u = 0; u < 4; u++) cp16(bdst + (sf4+u)*16, bsp + (sf4+u)*4);  \
    } while(0)

    float acc[4][4][4];
    #pragma unroll
    for (int mi = 0; mi < 4; mi++)
        #pragma unroll
        for (int ni = 0; ni < 4; ni++)
            #pragma unroll
            for (int r = 0; r < 4; r++) acc[mi][ni][r] = 0.f;

    K1G_LOAD(0, 0); cp_commit();

    #pragma unroll
    for (int kb = 0; kb < 4; kb++){
        if (kb < 3){ K1G_LOAD(kb+1, (kb+1)&1); cp_commit(); }
        if (kb < 3) cp_wait<1>(); else cp_wait<0>();
        __syncthreads();
        const uint32_t* Au = (const uint32_t*)sm + (kb&1)*4608;
        const uint32_t* Bu = (const uint32_t*)(sm + 36864) + (kb&1)*4608;
        #pragma unroll
        for (int k8 = 0; k8 < 4; k8++){
            int kof = k8*8 + t4;
            uint32_t af[4][4];
            #pragma unroll
            for (int mi = 0; mi < 4; mi++){
                int base = (WM + mi*16 + g)*36 + kof;
                af[mi][0] = Au[base];         af[mi][1] = Au[base + 8*36];
                af[mi][2] = Au[base + 4];     af[mi][3] = Au[base + 8*36 + 4];
            }
            #pragma unroll
            for (int ni = 0; ni < 4; ni++){
                int bb = (WN + ni*8 + g)*36 + kof;
                uint32_t bf[2] = { Bu[bb], Bu[bb + 4] };
                #pragma unroll
                for (int mi = 0; mi < 4; mi++)
                    mma_tf32(acc[mi][ni], af[mi], bf);
            }
        }
        __syncthreads();
    }
    #undef K1G_LOAD

    // epilogue: sigmoid(LN-fold) -> sgs -> coalesced out
    #pragma unroll
    for (int mi = 0; mi < 4; mi++){
        int m = WM + mi*16 + g;
        float mu0 = smu[m],   iv0 = sinv[m];
        float mu1 = smu[m+8], iv1 = sinv[m+8];
        #pragma unroll
        for (int ni = 0; ni < 4; ni++){
            int dl = WN + ni*8 + 2*t4, dl1 = dl + 1;
            float S0 = cS1[dl], S1 = cS1[dl1], B0 = cB1[dl], B1 = cB1[dl1];
            sgs[m*130 + dl]      = sigmoidf_fast(iv0*(acc[mi][ni][0] - mu0*S0) + B0);
            sgs[m*130 + dl1]     = sigmoidf_fast(iv0*(acc[mi][ni][1] - mu0*S1) + B1);
            sgs[(m+8)*130 + dl]  = sigmoidf_fast(iv1*(acc[mi][ni][2] - mu1*S0) + B0);
            sgs[(m+8)*130 + dl1] = sigmoidf_fast(iv1*(acc[mi][ni][3] - mu1*S1) + B1);
        }
    }
    __syncthreads();
    float* dst = g_sg + (size_t)m0 * 128;
    #pragma unroll
    for (int u = 0; u < 64; u++){
        int idx = t + u*256;
        int m = idx >> 7, d = idx & 127;
        dst[idx] = sgs[m*130 + d];
    }
}

// ---------------- k2: triangle, 128x256 tile, warp 64x64, cp.async -----------
#define K2_SMEM 110592

__global__ void __launch_bounds__(256, 1)
k2_kernel(){
    extern __shared__ char sm[];
    uint32_t sbase = smem_u32(sm);

    int t = threadIdx.x, wid = t >> 5, lane = t & 31;
    int g = lane >> 2, t4 = lane & 3;
    int WM = (wid >> 2) * 64, WN = (wid & 3) * 64;

    int c  = blockIdx.z;
    int i0 = blockIdx.y * 128;
    int j0 = blockIdx.x * 256;
    const float* Ap = g_a + (size_t)c*PLANE + (size_t)i0*NN;
    const float* Bp = g_b + (size_t)c*PLANE + (size_t)j0*NN;

    int srow = t >> 1, sf4 = (t & 1) * 4;

    #define K2_LOAD(kb, buf) do {                                              \
        uint32_t adst = sbase + ((buf)*4608 + srow*36)*4;                      \
        const float* asp = Ap + (size_t)srow*NN + (kb)*32;                     \
        _Pragma("unroll")                                                      \
        for (int u = 0; u < 4; u++) cp16(adst + (sf4+u)*16, asp + (sf4+u)*4);  \
        uint32_t bdst = sbase + 36864 + ((buf)*9216 + t*36)*4;                 \
        const float* bsp = Bp + (size_t)t*NN + (kb)*32;                        \
        _Pragma("unroll")                                                      \
        for (int u = 0; u < 8; u++) cp16(bdst + u*16, bsp + u*4);              \
    } while(0)

    float acc[4][8][4];
    #pragma unroll
    for (int mi = 0; mi < 4; mi++)
        #pragma unroll
        for (int ni = 0; ni < 8; ni++)
            #pragma unroll
            for (int r = 0; r < 4; r++) acc[mi][ni][r] = 0.f;

    K2_LOAD(0, 0); cp_commit();

    for (int kb = 0; kb < 16; kb++){
        if (kb < 15){ K2_LOAD(kb+1, (kb+1)&1); cp_commit(); }
        if (kb < 15) cp_wait<1>(); else cp_wait<0>();
        __syncthreads();
        const uint32_t* Au = (const uint32_t*)sm + (kb&1)*4608;
        const uint32_t* Bu = (const uint32_t*)(sm + 36864) + (kb&1)*9216;
        #pragma unroll
        for (int k8 = 0; k8 < 4; k8++){
            int kof = k8*8 + t4;
            uint32_t af[4][4];
            #pragma unroll
            for (int mi = 0; mi < 4; mi++){
                int base = (WM + mi*16 + g)*36 + kof;
                af[mi][0] = Au[base];         af[mi][1] = Au[base + 8*36];
                af[mi][2] = Au[base + 4];     af[mi][3] = Au[base + 8*36 + 4];
            }
            uint32_t bf[8][2];
            #pragma unroll
            for (int ni = 0; ni < 8; ni++){
                int bb = (WN + ni*8 + g)*36 + kof;
                bf[ni][0] = Bu[bb]; bf[ni][1] = Bu[bb + 4];
            }
            #pragma unroll
            for (int mi = 0; mi < 4; mi++)
                #pragma unroll
                for (int ni = 0; ni < 8; ni++)
                    mma_tf32(acc[mi][ni], af[mi], bf[ni]);
        }
        __syncthreads();
    }
    #undef K2_LOAD

    float* Tp = g_t + (size_t)c*PLANE;
    #pragma unroll
    for (int mi = 0; mi < 4; mi++){
        int r0 = i0 + WM + mi*16 + g;
        #pragma unroll
        for (int ni = 0; ni < 8; ni++){
            int cc = j0 + WN + ni*8 + 2*t4;
            *(float2*)(Tp + (size_t)r0*NN + cc)     = make_float2(acc[mi][ni][0], acc[mi][ni][1]);
            *(float2*)(Tp + (size_t)(r0+8)*NN + cc) = make_float2(acc[mi][ni][2], acc[mi][ni][3]);
        }
    }
}

// ---------------- k3: LN(t) folded + out-GEMM + gate (unchanged) -------------
#define K3_SMEM 101376

__global__ void __launch_bounds__(256, 2)
k3_kernel(float* __restrict__ out){
    extern __shared__ char sm[];
    float*  ts    = (float*)sm;
    float*  mu_s  = (float*)(sm + 34816);
    float*  inv_s = (float*)(sm + 35072);
    float2* ws    = (float2*)(sm + 35328);
    float2* sgs   = (float2*)(sm + 68096);
    ull* ws_u = (ull*)ws;

    int t   = threadIdx.x;
    int bid = blockIdx.x;
    int i   = bid >> 3;
    int j0  = (bid & 7) * 64;
    size_t base = (size_t)(i*NN + j0) * 64;

    #pragma unroll
    for (int u = 0; u < 8; u++){
        int idx = t + u*256;
        int c = idx >> 4, f4 = idx & 15;
        float4 v = *(const float4*)(g_t + ((size_t)c*NN + i)*NN + j0 + f4*4);
        *(float4*)&ts[c*68 + f4*4] = v;
    }
    {
        const float2* sg2 = (const float2*)g_sg;
        #pragma unroll
        for (int u = 0; u < 16; u++){
            int gg  = t + u*256;
            int pos = gg >> 6, dpl = gg & 63;
            sgs[pos*65 + dpl] = sg2[base + gg];
        }
    }
    __syncthreads();

    if (t < 64){
        float s = 0.f, s2 = 0.f;
        #pragma unroll 8
        for (int c = 0; c < 128; c++){ float v = ts[c*68 + t]; s += v; s2 += v*v; }
        float m   = s * (1.f/128.f);
        float var = s2 * (1.f/128.f) - m*m;
        mu_s[t]  = m;
        inv_s[t] = rsqrtf(var + 1e-5f);
    }
    __syncthreads();

    int jg = t & 15, pg = t >> 4;

    for (int ch = 0; ch < 2; ch++){
        #pragma unroll
        for (int u = 0; u < 16; u++){ int idx = t + u*256; ws[idx] = g_Wo2[ch*4096 + idx]; }
        __syncthreads();

        ull acc[4][2];
        #pragma unroll
        for (int q = 0; q < 4; q++){ acc[q][0] = 0ull; acc[q][1] = 0ull; }
        #pragma unroll 4
        for (int c = 0; c < 128; c++){
            ull xb[4];
            #pragma unroll
            for (int q = 0; q < 4; q++){ float xv = ts[c*68 + jg + 16*q]; xb[q] = pack2(xv, xv); }
            #pragma unroll
            for (int pp = 0; pp < 2; pp++){
                ull w = ws_u[(pg*2 + pp)*128 + c];
                #pragma unroll
                for (int q = 0; q < 4; q++) acc[q][pp] = ffma2(xb[q], w, acc[q][pp]);
            }
        }

        #pragma unroll
        for (int q = 0; q < 4; q++){
            int pos = jg + 16*q;
            float mui = mu_s[pos], ivi = inv_s[pos];
            #pragma unroll
            for (int pp = 0; pp < 2; pp++){
                int dpl = ch*32 + pg*2 + pp, d0 = dpl*2;
                float2 aa = unpack2(acc[q][pp]);
                float o0 = ivi*(aa.x - mui*g_So[d0])   + g_Bo[d0];
                float o1 = ivi*(aa.y - mui*g_So[d0+1]) + g_Bo[d0+1];
                float2 sg = sgs[pos*65 + dpl];
                sgs[pos*65 + dpl] = make_float2(o0*sg.x, o1*sg.y);
            }
        }
        __syncthreads();
    }

    {
        float2* out2 = (float2*)out;
        #pragma unroll
        for (int u = 0; u < 16; u++){
            int gg  = t + u*256;
            int pos = gg >> 6, dpl = gg & 63;
            out2[base + gg] = sgs[pos*65 + dpl];
        }
    }
}

// ---------------- launch -----------------------------------------------------
extern "C" void kernel_launch(void* const* d_in, const int* in_sizes, int n_in,
                              void* d_out, int out_size){
    const float* act  = (const float*)d_in[0];
    const float* mask = (const float*)d_in[1];
    const float* lnw  = (const float*)d_in[2];
    const float* lnb  = (const float*)d_in[3];
    const float* Wp   = (const float*)d_in[4];
    const float* Wg   = (const float*)d_in[5];
    const float* lcw  = (const float*)d_in[6];
    const float* lcb  = (const float*)d_in[7];
    const float* Wo   = (const float*)d_in[8];
    const float* Wl   = (const float*)d_in[9];

    cudaFuncSetAttribute(k1pg_kernel, cudaFuncAttributeMaxDynamicSharedMemorySize, K1PG_SMEM);
    cudaFuncSetAttribute(k1gl_kernel, cudaFuncAttributeMaxDynamicSharedMemorySize, K1GL_SMEM);
    cudaFuncSetAttribute(k2_kernel,   cudaFuncAttributeMaxDynamicSharedMemorySize, K2_SMEM);
    cudaFuncSetAttribute(k3_kernel,   cudaFuncAttributeMaxDynamicSharedMemorySize, K3_SMEM);

    prep_kernel<<<768, 128>>>(lnw, lnb, Wp, Wg, lcw, lcb, Wo, Wl);
    k0_kernel<<<32768, 256>>>(act);
    k1pg_kernel<<<dim3(2048, 2), 256, K1PG_SMEM>>>(mask);
    k1gl_kernel<<<2048, 256, K1GL_SMEM>>>();
    k2_kernel<<<dim3(2, 4, 128), 256, K2_SMEM>>>();
    k3_kernel<<<4096, 256, K3_SMEM>>>((float*)d_out);
}